// round 5
// baseline (speedup 1.0000x reference)
#include <cuda_runtime.h>
#include <cuda_bf16.h>
#include <cstdint>

#define S_LEN 2048
#define D_DIM 1024
#define BATCH 4
#define MTOT  (BATCH * S_LEN)   // 8192

// Scratch (static device arrays — allocation-guard safe)
__device__ float g_qkv[(size_t)3 * MTOT * D_DIM];          // Q,K,V each [4,2048,1024]
__device__ float g_scores[(size_t)BATCH * S_LEN * S_LEN];  // [4,2048,2048]
__device__ float g_wt[(size_t)3 * D_DIM * D_DIM];          // W transposed [3,e,d]
__device__ float g_vt[(size_t)BATCH * D_DIM * S_LEN];      // V transposed [4,e,s]

// ---------------------------------------------------------------------------
// Tiled transpose: out[b][c][r] = in[b][r][c]
// ---------------------------------------------------------------------------
__global__ void transpose_k(const float* __restrict__ in, float* __restrict__ out,
                            int R, int C) {
    __shared__ float t[32][33];
    size_t boff = (size_t)blockIdx.z * R * C;
    in += boff; out += boff;
    int c0 = blockIdx.x * 32, r0 = blockIdx.y * 32;
    int tx = threadIdx.x, ty = threadIdx.y;
    #pragma unroll
    for (int j = ty; j < 32; j += 8)
        t[j][tx] = in[(size_t)(r0 + j) * C + c0 + tx];
    __syncthreads();
    #pragma unroll
    for (int j = ty; j < 32; j += 8)
        out[(size_t)(c0 + j) * R + r0 + tx] = t[tx][j];
}

// ---------------------------------------------------------------------------
// bf16x2-split tensor-core GEMM:  C[m][n] (+= alpha *) A[m][k] * B[n][k]^T
//   A row-major [M][K] (ld=K), B row-major [N][K] (ld=K, i.e. k-contiguous),
//   C row-major [M][N]. Batched via blockIdx.z with element strides sA/sB/sC.
//   fp32 operands split into bf16 hi + bf16 lo at smem store; 3 MMAs per
//   product (hi*hi + hi*lo + lo*hi) -> ~2^-16 relative error per stage.
// Block tile 128x128, BK=16, 256 threads, 8 warps as 4(M) x 2(N),
// warp tile 32x64 -> 2x8 m16n8k16 tiles per warp.
// ---------------------------------------------------------------------------
#define SSTR 12  // smem row stride in u32 (bf16x2) units: 8 data + 4 pad (conflict-free)

__device__ __forceinline__ void mma16816(float* c, const uint32_t* a,
                                         uint32_t b0, uint32_t b1) {
    asm volatile(
        "mma.sync.aligned.m16n8k16.row.col.f32.bf16.bf16.f32 "
        "{%0,%1,%2,%3}, {%4,%5,%6,%7}, {%8,%9}, {%0,%1,%2,%3};\n"
        : "+f"(c[0]), "+f"(c[1]), "+f"(c[2]), "+f"(c[3])
        : "r"(a[0]), "r"(a[1]), "r"(a[2]), "r"(a[3]), "r"(b0), "r"(b1));
}

__device__ __forceinline__ void split_store4(uint32_t* hi, uint32_t* lo,
                                             int idx, float4 v) {
    __nv_bfloat162 h01 = __floats2bfloat162_rn(v.x, v.y);
    __nv_bfloat162 h23 = __floats2bfloat162_rn(v.z, v.w);
    __nv_bfloat162 l01 = __floats2bfloat162_rn(v.x - __low2float(h01),
                                               v.y - __high2float(h01));
    __nv_bfloat162 l23 = __floats2bfloat162_rn(v.z - __low2float(h23),
                                               v.w - __high2float(h23));
    uint2 h, l;
    h.x = *reinterpret_cast<uint32_t*>(&h01);
    h.y = *reinterpret_cast<uint32_t*>(&h23);
    l.x = *reinterpret_cast<uint32_t*>(&l01);
    l.y = *reinterpret_cast<uint32_t*>(&l23);
    *reinterpret_cast<uint2*>(hi + idx) = h;
    *reinterpret_cast<uint2*>(lo + idx) = l;
}

__global__ __launch_bounds__(256) void gemm3(
    const float* __restrict__ A, const float* __restrict__ B,
    float* __restrict__ C, int M, int N, int K,
    long sA, long sB, long sC, float alpha)
{
    __shared__ __align__(16) uint32_t As_hi[128 * SSTR];
    __shared__ __align__(16) uint32_t As_lo[128 * SSTR];
    __shared__ __align__(16) uint32_t Bs_hi[128 * SSTR];
    __shared__ __align__(16) uint32_t Bs_lo[128 * SSTR];

    A += (long)blockIdx.z * sA;
    B += (long)blockIdx.z * sB;
    C += (long)blockIdx.z * sC;

    const int tid  = threadIdx.x;
    const int lane = tid & 31, wid = tid >> 5;
    const int wm = wid >> 1, wn = wid & 1;       // 4 x 2 warp grid
    const int lr = lane >> 2, lc = lane & 3;
    const long bm = (long)blockIdx.y * 128, bn = (long)blockIdx.x * 128;

    float acc[2][8][4];
    #pragma unroll
    for (int i = 0; i < 2; i++)
        #pragma unroll
        for (int j = 0; j < 8; j++)
            #pragma unroll
            for (int q = 0; q < 4; q++) acc[i][j][q] = 0.f;

    // gmem load mapping: each thread owns 2 float4 per tile-side per iter
    const int row = tid >> 2;          // 0..63
    const int kc  = tid & 3;           // float4 within BK=16
    const float* Aptr = A + (bm + row) * (long)K + 4 * kc;
    const float* Bptr = B + (bn + row) * (long)K + 4 * kc;
    const int sidx0 = row * SSTR + 2 * kc;
    const int sidx1 = (row + 64) * SSTR + 2 * kc;

    float4 va0 = *(const float4*)(Aptr);
    float4 va1 = *(const float4*)(Aptr + 64L * K);
    float4 vb0 = *(const float4*)(Bptr);
    float4 vb1 = *(const float4*)(Bptr + 64L * K);

    const int nIter = K >> 4;
    for (int kt = 0; kt < nIter; kt++) {
        __syncthreads();  // previous compute done reading smem
        split_store4(As_hi, As_lo, sidx0, va0);
        split_store4(As_hi, As_lo, sidx1, va1);
        split_store4(Bs_hi, Bs_lo, sidx0, vb0);
        split_store4(Bs_hi, Bs_lo, sidx1, vb1);
        __syncthreads();

        if (kt + 1 < nIter) {  // overlap next-tile LDG with compute
            const float* Ap = Aptr + (long)(kt + 1) * 16;
            const float* Bp = Bptr + (long)(kt + 1) * 16;
            va0 = *(const float4*)(Ap);
            va1 = *(const float4*)(Ap + 64L * K);
            vb0 = *(const float4*)(Bp);
            vb1 = *(const float4*)(Bp + 64L * K);
        }

        // A fragments (hi & lo) for both m-tiles
        uint32_t ah[2][4], al[2][4];
        #pragma unroll
        for (int mi = 0; mi < 2; mi++) {
            int r0 = (wm * 32 + mi * 16 + lr) * SSTR;
            int r8 = r0 + 8 * SSTR;
            ah[mi][0] = As_hi[r0 + lc];     ah[mi][1] = As_hi[r8 + lc];
            ah[mi][2] = As_hi[r0 + 4 + lc]; ah[mi][3] = As_hi[r8 + 4 + lc];
            al[mi][0] = As_lo[r0 + lc];     al[mi][1] = As_lo[r8 + lc];
            al[mi][2] = As_lo[r0 + 4 + lc]; al[mi][3] = As_lo[r8 + 4 + lc];
        }
        #pragma unroll
        for (int ni = 0; ni < 8; ni++) {
            int nb = (wn * 64 + ni * 8 + lr) * SSTR;
            uint32_t bh0 = Bs_hi[nb + lc], bh1 = Bs_hi[nb + 4 + lc];
            uint32_t bl0 = Bs_lo[nb + lc], bl1 = Bs_lo[nb + 4 + lc];
            #pragma unroll
            for (int mi = 0; mi < 2; mi++) {
                mma16816(acc[mi][ni], ah[mi], bh0, bh1);  // hi*hi
                mma16816(acc[mi][ni], ah[mi], bl0, bl1);  // hi*lo
                mma16816(acc[mi][ni], al[mi], bh0, bh1);  // lo*hi
            }
        }
    }

    // epilogue
    #pragma unroll
    for (int mi = 0; mi < 2; mi++) {
        long r0 = bm + wm * 32 + mi * 16 + lr;
        #pragma unroll
        for (int ni = 0; ni < 8; ni++) {
            long col = bn + wn * 64 + ni * 8 + 2 * lc;
            float2 v0 = make_float2(alpha * acc[mi][ni][0], alpha * acc[mi][ni][1]);
            float2 v1 = make_float2(alpha * acc[mi][ni][2], alpha * acc[mi][ni][3]);
            *(float2*)(C + r0 * N + col)       = v0;
            *(float2*)(C + (r0 + 8) * N + col) = v1;
        }
    }
}

// ---------------------------------------------------------------------------
// Row softmax over 2048 columns. One CTA (256 thr) per row, 8 elems/thread.
// ---------------------------------------------------------------------------
__global__ __launch_bounds__(256) void softmax_k(float* __restrict__ S) {
    float* row = S + (size_t)blockIdx.x * 2048;
    const int tid = threadIdx.x;
    const int wid = tid >> 5, lane = tid & 31;
    __shared__ float smax[8], ssum[8];

    float v[8];
    #pragma unroll
    for (int i = 0; i < 8; i++) v[i] = row[tid + 256 * i];

    float m = v[0];
    #pragma unroll
    for (int i = 1; i < 8; i++) m = fmaxf(m, v[i]);
    #pragma unroll
    for (int o = 16; o > 0; o >>= 1) m = fmaxf(m, __shfl_xor_sync(0xffffffffu, m, o));
    if (lane == 0) smax[wid] = m;
    __syncthreads();
    m = smax[0];
    #pragma unroll
    for (int w = 1; w < 8; w++) m = fmaxf(m, smax[w]);

    float s = 0.f;
    #pragma unroll
    for (int i = 0; i < 8; i++) { v[i] = __expf(v[i] - m); s += v[i]; }
    #pragma unroll
    for (int o = 16; o > 0; o >>= 1) s += __shfl_xor_sync(0xffffffffu, s, o);
    if (lane == 0) ssum[wid] = s;
    __syncthreads();
    s = 0.f;
    #pragma unroll
    for (int w = 0; w < 8; w++) s += ssum[w];

    float inv = 1.0f / s;
    #pragma unroll
    for (int i = 0; i < 8; i++) row[tid + 256 * i] = v[i] * inv;
}

// ---------------------------------------------------------------------------
// kernel_launch: transpose W -> QKV gemm -> transpose V -> scores gemm ->
//                softmax -> out gemm.  All plain launches (graph-capturable).
// ---------------------------------------------------------------------------
extern "C" void kernel_launch(void* const* d_in, const int* in_sizes, int n_in,
                              void* d_out, int out_size) {
    const float* x = (const float*)d_in[0];   // [4,2048,1024]
    const float* w = (const float*)d_in[1];   // [3,1024,1024]
    float* out = (float*)d_out;               // [4,2048,1024] fp32

    float *qkv = nullptr, *scores = nullptr, *wt = nullptr, *vt = nullptr;
    cudaGetSymbolAddress((void**)&qkv, g_qkv);
    cudaGetSymbolAddress((void**)&scores, g_scores);
    cudaGetSymbolAddress((void**)&wt, g_wt);
    cudaGetSymbolAddress((void**)&vt, g_vt);

    // 1) W[h][d][e] -> Wt[h][e][d]
    transpose_k<<<dim3(32, 32, 3), dim3(32, 8)>>>(w, wt, 1024, 1024);

    // 2) QKV: [8192,1024] = x @ W[h]  (B operand = Wt, [n=e][k=d])
    gemm3<<<dim3(8, 64, 3), 256>>>(x, wt, qkv,
                                   8192, 1024, 1024,
                                   0L, 1024L * 1024, 8192L * 1024, 1.0f);

    // 3) V[b][s][e] -> Vt[b][e][s]
    transpose_k<<<dim3(32, 64, 4), dim3(32, 8)>>>(qkv + 2L * 8192 * 1024, vt,
                                                  2048, 1024);

    // 4) scores[b] = (Q[b] @ K[b]^T) / 32   (B operand = K, already [n=s_k][k=e])
    gemm3<<<dim3(16, 16, 4), 256>>>(qkv, qkv + 8192L * 1024, scores,
                                    2048, 2048, 1024,
                                    2048L * 1024, 2048L * 1024, 2048L * 2048,
                                    0.03125f);

    // 5) softmax over keys
    softmax_k<<<8192, 256>>>(scores);

    // 6) out[b] = attn[b] @ V[b]   (B operand = Vt, [n=e][k=s])
    gemm3<<<dim3(8, 16, 4), 256>>>(scores, vt, out,
                                   2048, 1024, 2048,
                                   2048L * 2048, 1024L * 2048, 2048L * 1024,
                                   1.0f);
}

// round 7
// speedup vs baseline: 1.0700x; 1.0700x over previous
#include <cuda_runtime.h>
#include <cuda_bf16.h>
#include <cstdint>

#define S_LEN 2048
#define D_DIM 1024
#define BATCH 4
#define MTOT  (BATCH * S_LEN)   // 8192

// Scratch (static device arrays — allocation-guard safe)
__device__ float g_qkv[(size_t)3 * MTOT * D_DIM];          // Q,K,V each [4,2048,1024]
__device__ float g_scores[(size_t)BATCH * S_LEN * S_LEN];  // [4,2048,2048]
__device__ float g_wt[(size_t)3 * D_DIM * D_DIM];          // W transposed [3,e,d]
__device__ float g_vt[(size_t)BATCH * D_DIM * S_LEN];      // V transposed [4,e,s]

// ---------------------------------------------------------------------------
// Tiled transpose: out[b][c][r] = in[b][r][c]
// ---------------------------------------------------------------------------
__global__ void transpose_k(const float* __restrict__ in, float* __restrict__ out,
                            int R, int C) {
    __shared__ float t[32][33];
    size_t boff = (size_t)blockIdx.z * R * C;
    in += boff; out += boff;
    int c0 = blockIdx.x * 32, r0 = blockIdx.y * 32;
    int tx = threadIdx.x, ty = threadIdx.y;
    #pragma unroll
    for (int j = ty; j < 32; j += 8)
        t[j][tx] = in[(size_t)(r0 + j) * C + c0 + tx];
    __syncthreads();
    #pragma unroll
    for (int j = ty; j < 32; j += 8)
        out[(size_t)(c0 + j) * R + r0 + tx] = t[tx][j];
}

// ---------------------------------------------------------------------------
// bf16x2-split tensor-core GEMM (legacy mma.sync path, sm_103-safe):
//   C[m][n] = alpha * A[m][k] * B[n][k]^T
//   CTA tile 128x256, warp tile 64x64 (8 warps as 2x4), BK=32,
//   2-stage smem double buffer, 1 sync per chunk, ldmatrix fragment loads.
//   fp32 split to bf16 hi+lo at STS; 3 MMAs per product (hh + hl + lh).
// ---------------------------------------------------------------------------
#define BM 128
#define BN 256
#define RS 20                        // smem row stride in u32 (16 data + 4 pad)
#define A_U32 (128 * RS)             // 2560
#define B_U32 (256 * RS)             // 5120
#define ST_U32 (2 * A_U32 + 2 * B_U32)  // 15360 u32 per stage
#define OFF_AL_B (A_U32 * 4)             // byte offsets within stage
#define OFF_BH_B (2 * A_U32 * 4)
#define OFF_BL_B ((2 * A_U32 + B_U32) * 4)
#define STAGE_B  (ST_U32 * 4)            // 61440
#define SMEM_BYTES (2 * STAGE_B)         // 122880

__device__ __forceinline__ uint32_t smem_u32(const void* p) {
    uint32_t a;
    asm("{ .reg .u64 t; cvta.to.shared.u64 t, %1; cvt.u32.u64 %0, t; }"
        : "=r"(a) : "l"(p));
    return a;
}

__device__ __forceinline__ void ldmx4(uint32_t* d, uint32_t addr) {
    asm volatile("ldmatrix.sync.aligned.m8n8.x4.shared.b16 {%0,%1,%2,%3}, [%4];"
                 : "=r"(d[0]), "=r"(d[1]), "=r"(d[2]), "=r"(d[3]) : "r"(addr));
}

__device__ __forceinline__ void mma16816(float* c, const uint32_t* a,
                                         uint32_t b0, uint32_t b1) {
    asm volatile(
        "mma.sync.aligned.m16n8k16.row.col.f32.bf16.bf16.f32 "
        "{%0,%1,%2,%3}, {%4,%5,%6,%7}, {%8,%9}, {%0,%1,%2,%3};\n"
        : "+f"(c[0]), "+f"(c[1]), "+f"(c[2]), "+f"(c[3])
        : "r"(a[0]), "r"(a[1]), "r"(a[2]), "r"(a[3]), "r"(b0), "r"(b1));
}

__device__ __forceinline__ void split4(float4 v, uint2& h, uint2& l) {
    __nv_bfloat162 h01 = __floats2bfloat162_rn(v.x, v.y);
    __nv_bfloat162 h23 = __floats2bfloat162_rn(v.z, v.w);
    __nv_bfloat162 l01 = __floats2bfloat162_rn(v.x - __low2float(h01),
                                               v.y - __high2float(h01));
    __nv_bfloat162 l23 = __floats2bfloat162_rn(v.z - __low2float(h23),
                                               v.w - __high2float(h23));
    h.x = *reinterpret_cast<uint32_t*>(&h01);
    h.y = *reinterpret_cast<uint32_t*>(&h23);
    l.x = *reinterpret_cast<uint32_t*>(&l01);
    l.y = *reinterpret_cast<uint32_t*>(&l23);
}

__global__ __launch_bounds__(256, 1) void gemm_tc(
    const float* __restrict__ A, const float* __restrict__ B,
    float* __restrict__ C, int M, int N, int K,
    long sA, long sB, long sC, float alpha)
{
    extern __shared__ __align__(128) uint32_t sm[];
    const uint32_t sbase = smem_u32(sm);
    const int tid = threadIdx.x;
    const int lane = tid & 31, wid = tid >> 5;
    const int wm = wid >> 2, wn = wid & 3;          // 2(M) x 4(N) warps

    A += (long)blockIdx.z * sA;
    B += (long)blockIdx.z * sB;
    C += (long)blockIdx.z * sC;
    const long bm = (long)blockIdx.y * BM, bn = (long)blockIdx.x * BN;

    float acc[4][8][4];
    #pragma unroll
    for (int i = 0; i < 4; i++)
        #pragma unroll
        for (int j = 0; j < 8; j++)
            #pragma unroll
            for (int q = 0; q < 4; q++) acc[i][j][q] = 0.f;

    // ---- load / store mapping ----
    const int tr  = tid >> 3;                        // 0..31 base row
    const int tc4 = tid & 7;                         // f4 col within 32-float row
    const float* Ap = A + (bm + tr) * (long)K + 4 * tc4;
    const float* Bp = B + (bn + tr) * (long)K + 4 * tc4;
    const int sO = tr * RS + 2 * tc4;                // u32 offset; +32*RS per j

    // ---- ldmatrix per-lane byte offsets (within a tile) ----
    uint32_t aOff[4], bOff[4];
    {
        int l15 = lane & 15, lh = lane >> 4;
        #pragma unroll
        for (int mi = 0; mi < 4; mi++)
            aOff[mi] = (uint32_t)((wm * 64 + mi * 16 + l15) * (RS * 4) + lh * 16);
        int g = lane >> 3, r8 = lane & 7;
        #pragma unroll
        for (int nj = 0; nj < 4; nj++)
            bOff[nj] = (uint32_t)((wn * 64 + nj * 16 + ((g >> 1) & 1) * 8 + r8) * (RS * 4)
                                  + (g & 1) * 16);
    }

    const int nc = K >> 5;   // BK=32 chunks

    // ---- prologue: chunk 0 -> stage 0 ----
    {
        uint32_t* st = sm;
        #pragma unroll
        for (int j = 0; j < 4; j++) {
            float4 v = *(const float4*)(Ap + (long)(32 * j) * K);
            uint2 h, l; split4(v, h, l);
            *reinterpret_cast<uint2*>(st + sO + 32 * RS * j) = h;
            *reinterpret_cast<uint2*>(st + A_U32 + sO + 32 * RS * j) = l;
        }
        #pragma unroll
        for (int j = 0; j < 8; j++) {
            float4 v = *(const float4*)(Bp + (long)(32 * j) * K);
            uint2 h, l; split4(v, h, l);
            *reinterpret_cast<uint2*>(st + 2 * A_U32 + sO + 32 * RS * j) = h;
            *reinterpret_cast<uint2*>(st + 2 * A_U32 + B_U32 + sO + 32 * RS * j) = l;
        }
    }
    __syncthreads();

    for (int kt = 0; kt < nc; kt++) {
        // prefetch chunk kt+1 into registers (overlaps compute)
        float4 pa[4], pb[8];
        if (kt + 1 < nc) {
            const float* a1 = Ap + (kt + 1) * 32;
            const float* b1 = Bp + (kt + 1) * 32;
            #pragma unroll
            for (int j = 0; j < 4; j++) pa[j] = *(const float4*)(a1 + (long)(32 * j) * K);
            #pragma unroll
            for (int j = 0; j < 8; j++) pb[j] = *(const float4*)(b1 + (long)(32 * j) * K);
        }

        // compute stage kt&1
        const uint32_t stO = sbase + (uint32_t)((kt & 1) * STAGE_B);
        #pragma unroll
        for (int s = 0; s < 2; s++) {
            uint32_t ah[4][4], al[4][4];
            #pragma unroll
            for (int mi = 0; mi < 4; mi++) {
                uint32_t ad = stO + aOff[mi] + s * 32;
                ldmx4(ah[mi], ad);
                ldmx4(al[mi], ad + OFF_AL_B);
            }
            #pragma unroll
            for (int nj = 0; nj < 4; nj++) {
                uint32_t bd = stO + OFF_BH_B + bOff[nj] + s * 32;
                uint32_t bh[4], bl[4];
                ldmx4(bh, bd);
                ldmx4(bl, bd + (OFF_BL_B - OFF_BH_B));
                #pragma unroll
                for (int mi = 0; mi < 4; mi++) {
                    mma16816(acc[mi][2 * nj],     ah[mi], bh[0], bh[1]);
                    mma16816(acc[mi][2 * nj],     ah[mi], bl[0], bl[1]);
                    mma16816(acc[mi][2 * nj],     al[mi], bh[0], bh[1]);
                    mma16816(acc[mi][2 * nj + 1], ah[mi], bh[2], bh[3]);
                    mma16816(acc[mi][2 * nj + 1], ah[mi], bl[2], bl[3]);
                    mma16816(acc[mi][2 * nj + 1], al[mi], bh[2], bh[3]);
                }
            }
        }

        // store chunk kt+1 -> stage (kt+1)&1  (that stage was consumed in kt-1)
        if (kt + 1 < nc) {
            uint32_t* st = sm + ((kt + 1) & 1) * ST_U32;
            #pragma unroll
            for (int j = 0; j < 4; j++) {
                uint2 h, l; split4(pa[j], h, l);
                *reinterpret_cast<uint2*>(st + sO + 32 * RS * j) = h;
                *reinterpret_cast<uint2*>(st + A_U32 + sO + 32 * RS * j) = l;
            }
            #pragma unroll
            for (int j = 0; j < 8; j++) {
                uint2 h, l; split4(pb[j], h, l);
                *reinterpret_cast<uint2*>(st + 2 * A_U32 + sO + 32 * RS * j) = h;
                *reinterpret_cast<uint2*>(st + 2 * A_U32 + B_U32 + sO + 32 * RS * j) = l;
            }
        }
        __syncthreads();
    }

    // ---- epilogue ----
    #pragma unroll
    for (int mi = 0; mi < 4; mi++) {
        long r0 = bm + wm * 64 + mi * 16 + (lane >> 2);
        #pragma unroll
        for (int ni = 0; ni < 8; ni++) {
            long c = bn + wn * 64 + ni * 8 + 2 * (lane & 3);
            float2 v0 = make_float2(alpha * acc[mi][ni][0], alpha * acc[mi][ni][1]);
            float2 v1 = make_float2(alpha * acc[mi][ni][2], alpha * acc[mi][ni][3]);
            *(float2*)(C + r0 * N + c)       = v0;
            *(float2*)(C + (r0 + 8) * N + c) = v1;
        }
    }
}

// ---------------------------------------------------------------------------
// Row softmax over 2048 columns. One CTA (256 thr) per row, 8 elems/thread.
// ---------------------------------------------------------------------------
__global__ __launch_bounds__(256) void softmax_k(float* __restrict__ S) {
    float* row = S + (size_t)blockIdx.x * 2048;
    const int tid = threadIdx.x;
    const int wid = tid >> 5, lane = tid & 31;
    __shared__ float smax[8], ssum[8];

    float v[8];
    #pragma unroll
    for (int i = 0; i < 8; i++) v[i] = row[tid + 256 * i];

    float m = v[0];
    #pragma unroll
    for (int i = 1; i < 8; i++) m = fmaxf(m, v[i]);
    #pragma unroll
    for (int o = 16; o > 0; o >>= 1) m = fmaxf(m, __shfl_xor_sync(0xffffffffu, m, o));
    if (lane == 0) smax[wid] = m;
    __syncthreads();
    m = smax[0];
    #pragma unroll
    for (int w = 1; w < 8; w++) m = fmaxf(m, smax[w]);

    float s = 0.f;
    #pragma unroll
    for (int i = 0; i < 8; i++) { v[i] = __expf(v[i] - m); s += v[i]; }
    #pragma unroll
    for (int o = 16; o > 0; o >>= 1) s += __shfl_xor_sync(0xffffffffu, s, o);
    if (lane == 0) ssum[wid] = s;
    __syncthreads();
    s = 0.f;
    #pragma unroll
    for (int w = 0; w < 8; w++) s += ssum[w];

    float inv = 1.0f / s;
    #pragma unroll
    for (int i = 0; i < 8; i++) row[tid + 256 * i] = v[i] * inv;
}

// ---------------------------------------------------------------------------
// kernel_launch
// ---------------------------------------------------------------------------
extern "C" void kernel_launch(void* const* d_in, const int* in_sizes, int n_in,
                              void* d_out, int out_size) {
    const float* x = (const float*)d_in[0];   // [4,2048,1024]
    const float* w = (const float*)d_in[1];   // [3,1024,1024]
    float* out = (float*)d_out;               // [4,2048,1024] fp32

    float *qkv = nullptr, *scores = nullptr, *wt = nullptr, *vt = nullptr;
    cudaGetSymbolAddress((void**)&qkv, g_qkv);
    cudaGetSymbolAddress((void**)&scores, g_scores);
    cudaGetSymbolAddress((void**)&wt, g_wt);
    cudaGetSymbolAddress((void**)&vt, g_vt);

    static bool attr_done = false;
    if (!attr_done) {
        cudaFuncSetAttribute(gemm_tc, cudaFuncAttributeMaxDynamicSharedMemorySize,
                             SMEM_BYTES);
        attr_done = true;
    }

    // 1) W[h][d][e] -> Wt[h][e][d]
    transpose_k<<<dim3(32, 32, 3), dim3(32, 8)>>>(w, wt, 1024, 1024);

    // 2) QKV: [8192,1024] = x @ W[h]
    gemm_tc<<<dim3(4, 64, 3), 256, SMEM_BYTES>>>(x, wt, qkv,
                                                 8192, 1024, 1024,
                                                 0L, 1024L * 1024, 8192L * 1024, 1.0f);

    // 3) V[b][s][e] -> Vt[b][e][s]
    transpose_k<<<dim3(32, 64, 4), dim3(32, 8)>>>(qkv + 2L * 8192 * 1024, vt,
                                                  2048, 1024);

    // 4) scores[b] = (Q[b] @ K[b]^T) / 32
    gemm_tc<<<dim3(8, 16, 4), 256, SMEM_BYTES>>>(qkv, qkv + 8192L * 1024, scores,
                                                 2048, 2048, 1024,
                                                 2048L * 1024, 2048L * 1024,
                                                 2048L * 2048, 0.03125f);

    // 5) softmax over keys
    softmax_k<<<8192, 256>>>(scores);

    // 6) out[b] = attn[b] @ V[b]
    gemm_tc<<<dim3(4, 16, 4), 256, SMEM_BYTES>>>(scores, vt, out,
                                                 2048, 1024, 2048,
                                                 2048L * 2048, 1024L * 2048,
                                                 2048L * 1024, 1.0f);
}

// round 8
// speedup vs baseline: 1.2504x; 1.1686x over previous
#include <cuda_runtime.h>
#include <cuda_bf16.h>
#include <cstdint>

#define S_LEN 2048
#define D_DIM 1024
#define BATCH 4
#define MTOT  (BATCH * S_LEN)   // 8192

// ---------------- scratch (static device arrays; allocation-guard safe) ----
__device__ __nv_bfloat16 g_xh[(size_t)MTOT * D_DIM];        // x split hi
__device__ __nv_bfloat16 g_xl[(size_t)MTOT * D_DIM];        // x split lo
__device__ __nv_bfloat16 g_wth[(size_t)3 * D_DIM * D_DIM];  // W^T split hi [3][e][d]
__device__ __nv_bfloat16 g_wtl[(size_t)3 * D_DIM * D_DIM];
__device__ __nv_bfloat16 g_qkh[(size_t)2 * MTOT * D_DIM];   // Q then K, split hi
__device__ __nv_bfloat16 g_qkl[(size_t)2 * MTOT * D_DIM];
__device__ float         g_v[(size_t)MTOT * D_DIM];         // V fp32 [4][2048][1024]
__device__ __nv_bfloat16 g_vth[(size_t)BATCH * D_DIM * S_LEN]; // V^T split [4][e][s]
__device__ __nv_bfloat16 g_vtl[(size_t)BATCH * D_DIM * S_LEN];
__device__ float         g_scores[(size_t)BATCH * S_LEN * S_LEN];
__device__ __nv_bfloat16 g_ph[(size_t)BATCH * S_LEN * S_LEN];  // attn split
__device__ __nv_bfloat16 g_pl[(size_t)BATCH * S_LEN * S_LEN];

// ---------------- helpers ---------------------------------------------------
__device__ __forceinline__ uint32_t smem_u32(const void* p) {
    uint32_t a;
    asm("{ .reg .u64 t; cvta.to.shared.u64 t, %1; cvt.u32.u64 %0, t; }"
        : "=r"(a) : "l"(p));
    return a;
}

__device__ __forceinline__ void cpa16(uint32_t saddr, const void* g) {
    asm volatile("cp.async.cg.shared.global [%0], [%1], 16;"
                 :: "r"(saddr), "l"(g));
}
__device__ __forceinline__ void cpa_commit() {
    asm volatile("cp.async.commit_group;");
}
template <int N>
__device__ __forceinline__ void cpa_wait() {
    asm volatile("cp.async.wait_group %0;" :: "n"(N));
}

__device__ __forceinline__ void ldmx4(uint32_t* d, uint32_t addr) {
    asm volatile("ldmatrix.sync.aligned.m8n8.x4.shared.b16 {%0,%1,%2,%3}, [%4];"
                 : "=r"(d[0]), "=r"(d[1]), "=r"(d[2]), "=r"(d[3]) : "r"(addr));
}

__device__ __forceinline__ void mma16816(float* c, const uint32_t* a,
                                         uint32_t b0, uint32_t b1) {
    asm volatile(
        "mma.sync.aligned.m16n8k16.row.col.f32.bf16.bf16.f32 "
        "{%0,%1,%2,%3}, {%4,%5,%6,%7}, {%8,%9}, {%0,%1,%2,%3};\n"
        : "+f"(c[0]), "+f"(c[1]), "+f"(c[2]), "+f"(c[3])
        : "r"(a[0]), "r"(a[1]), "r"(a[2]), "r"(a[3]), "r"(b0), "r"(b1));
}

__device__ __forceinline__ void split4(float4 v, uint2& h, uint2& l) {
    __nv_bfloat162 h01 = __floats2bfloat162_rn(v.x, v.y);
    __nv_bfloat162 h23 = __floats2bfloat162_rn(v.z, v.w);
    __nv_bfloat162 l01 = __floats2bfloat162_rn(v.x - __low2float(h01),
                                               v.y - __high2float(h01));
    __nv_bfloat162 l23 = __floats2bfloat162_rn(v.z - __low2float(h23),
                                               v.w - __high2float(h23));
    h.x = *reinterpret_cast<uint32_t*>(&h01);
    h.y = *reinterpret_cast<uint32_t*>(&h23);
    l.x = *reinterpret_cast<uint32_t*>(&l01);
    l.y = *reinterpret_cast<uint32_t*>(&l23);
}

// ---------------- pre/post-processing kernels ------------------------------
// fp32 -> bf16 hi/lo, elementwise (float4 per thread)
__global__ __launch_bounds__(256) void split_f32(const float* __restrict__ in,
                                                 __nv_bfloat16* __restrict__ oh,
                                                 __nv_bfloat16* __restrict__ ol) {
    size_t i = (size_t)blockIdx.x * 256 + threadIdx.x;
    float4 v = reinterpret_cast<const float4*>(in)[i];
    uint2 h, l; split4(v, h, l);
    reinterpret_cast<uint2*>(oh)[i] = h;
    reinterpret_cast<uint2*>(ol)[i] = l;
}

// transpose + split: in fp32 [z][R][C] -> out hi/lo bf16 [z][C][R]
__global__ void transpose_split(const float* __restrict__ in,
                                __nv_bfloat16* __restrict__ oh,
                                __nv_bfloat16* __restrict__ ol,
                                int R, int C) {
    __shared__ float t[32][33];
    size_t boff = (size_t)blockIdx.z * R * C;
    in += boff; oh += boff; ol += boff;
    int c0 = blockIdx.x * 32, r0 = blockIdx.y * 32;
    int tx = threadIdx.x, ty = threadIdx.y;
    #pragma unroll
    for (int j = ty; j < 32; j += 8)
        t[j][tx] = in[(size_t)(r0 + j) * C + c0 + tx];
    __syncthreads();
    #pragma unroll
    for (int j = ty; j < 32; j += 8) {
        float v = t[tx][j];
        __nv_bfloat16 h = __float2bfloat16(v);
        __nv_bfloat16 l = __float2bfloat16(v - __bfloat162float(h));
        size_t o = (size_t)(c0 + j) * R + r0 + tx;
        oh[o] = h; ol[o] = l;
    }
}

// ---------------------------------------------------------------------------
// bf16 hi/lo split GEMM:  C[m][n] = alpha * (Ah+Al)[m][k] * (Bh+Bl)[n][k]^T
//   All operands pre-split bf16, row-major k-contiguous.
//   CTA 128x256, warps 2x4 (64x64 tiles), BK=64, 2-stage cp.async pipeline,
//   XOR-swizzled 128B smem rows, ldmatrix fragments, 3 MMAs per product.
//   MODE 0: C fp32.  MODE 1: C written as bf16 hi/lo pair (Ch, Cl).
// ---------------------------------------------------------------------------
#define BM 128
#define BN 256
#define AH_OFF 0
#define AL_OFF 16384
#define BH_OFF 32768
#define BL_OFF 65536
#define STG_B  98304
#define SMEM_BYTES (2 * STG_B)   // 196608

template <int MODE>
__global__ __launch_bounds__(256, 1) void gemm_bs(
    const __nv_bfloat16* __restrict__ Ah, const __nv_bfloat16* __restrict__ Al,
    const __nv_bfloat16* __restrict__ Bh, const __nv_bfloat16* __restrict__ Bl,
    float* __restrict__ Cf, __nv_bfloat16* __restrict__ Ch,
    __nv_bfloat16* __restrict__ Cl,
    int M, int N, int K, long sA, long sB, long sC, float alpha)
{
    extern __shared__ __align__(128) char smem[];
    const uint32_t sbase = smem_u32(smem);
    const int tid = threadIdx.x;
    const int lane = tid & 31, wid = tid >> 5;
    const int wm = wid >> 2, wn = wid & 3;   // 2(M) x 4(N)

    Ah += (long)blockIdx.z * sA;  Al += (long)blockIdx.z * sA;
    Bh += (long)blockIdx.z * sB;  Bl += (long)blockIdx.z * sB;
    const long bm = (long)blockIdx.y * BM, bn = (long)blockIdx.x * BN;

    float acc[4][8][4];
    #pragma unroll
    for (int i = 0; i < 4; i++)
        #pragma unroll
        for (int j = 0; j < 8; j++)
            #pragma unroll
            for (int q = 0; q < 4; q++) acc[i][j][q] = 0.f;

    // ---- cp.async mapping: thread -> (row = tid>>3, 16B-chunk = tid&7) ----
    const int arow = tid >> 3, ac = tid & 7;
    const __nv_bfloat16* gAh = Ah + (bm + arow) * (long)K + ac * 8;
    const __nv_bfloat16* gAl = Al + (bm + arow) * (long)K + ac * 8;
    const __nv_bfloat16* gBh = Bh + (bn + arow) * (long)K + ac * 8;
    const __nv_bfloat16* gBl = Bl + (bn + arow) * (long)K + ac * 8;
    const uint32_t sOff = (uint32_t)arow * 128u + (uint32_t)((ac ^ (arow & 7)) * 16);

    // ---- ldmatrix per-lane tile bases + swizzle masks ----
    const int l15 = lane & 15, lh = lane >> 4;
    const int g8 = lane >> 3, r8 = lane & 7;
    uint32_t aBase[4], aMsk[4], bBase[4], bMsk[4];
    #pragma unroll
    for (int mi = 0; mi < 4; mi++) {
        int r = wm * 64 + mi * 16 + l15;
        aBase[mi] = (uint32_t)r * 128u;
        aMsk[mi]  = (uint32_t)(r & 7);
    }
    #pragma unroll
    for (int nj = 0; nj < 4; nj++) {
        int r = wn * 64 + nj * 16 + ((g8 >> 1) & 1) * 8 + r8;
        bBase[nj] = (uint32_t)r * 128u;
        bMsk[nj]  = (uint32_t)(r & 7);
    }

    const int nc = K >> 6;   // BK=64 chunks (K is a multiple of 64 here)

    // issue one full stage of cp.asyncs for chunk kt into stage stg
    auto issue = [&](int kt, int stg) {
        uint32_t st = sbase + (uint32_t)stg * STG_B;
        const __nv_bfloat16* pah = gAh + (long)kt * 64;
        const __nv_bfloat16* pal = gAl + (long)kt * 64;
        const __nv_bfloat16* pbh = gBh + (long)kt * 64;
        const __nv_bfloat16* pbl = gBl + (long)kt * 64;
        #pragma unroll
        for (int i = 0; i < 4; i++) {
            cpa16(st + AH_OFF + sOff + i * 4096u, pah + (long)(32 * i) * K);
            cpa16(st + AL_OFF + sOff + i * 4096u, pal + (long)(32 * i) * K);
        }
        #pragma unroll
        for (int i = 0; i < 8; i++) {
            cpa16(st + BH_OFF + sOff + i * 4096u, pbh + (long)(32 * i) * K);
            cpa16(st + BL_OFF + sOff + i * 4096u, pbl + (long)(32 * i) * K);
        }
    };

    issue(0, 0); cpa_commit();
    issue(1, 1); cpa_commit();

    for (int kt = 0; kt < nc; kt++) {
        cpa_wait<1>();
        __syncthreads();

        const uint32_t stO = sbase + (uint32_t)(kt & 1) * STG_B;
        #pragma unroll
        for (int s = 0; s < 4; s++) {
            uint32_t ah[4][4], al[4][4];
            #pragma unroll
            for (int mi = 0; mi < 4; mi++) {
                uint32_t phys = ((uint32_t)(2 * s + lh)) ^ aMsk[mi];
                uint32_t ad = stO + aBase[mi] + phys * 16u;
                ldmx4(ah[mi], ad + AH_OFF);
                ldmx4(al[mi], ad + AL_OFF);
            }
            #pragma unroll
            for (int nj = 0; nj < 4; nj++) {
                uint32_t phys = ((uint32_t)(2 * s + (g8 & 1))) ^ bMsk[nj];
                uint32_t bd = stO + bBase[nj] + phys * 16u;
                uint32_t bh[4], bl[4];
                ldmx4(bh, bd + BH_OFF);
                ldmx4(bl, bd + BL_OFF);
                #pragma unroll
                for (int mi = 0; mi < 4; mi++) {
                    mma16816(acc[mi][2 * nj],     ah[mi], bh[0], bh[1]);
                    mma16816(acc[mi][2 * nj],     ah[mi], bl[0], bl[1]);
                    mma16816(acc[mi][2 * nj],     al[mi], bh[0], bh[1]);
                    mma16816(acc[mi][2 * nj + 1], ah[mi], bh[2], bh[3]);
                    mma16816(acc[mi][2 * nj + 1], ah[mi], bl[2], bl[3]);
                    mma16816(acc[mi][2 * nj + 1], al[mi], bh[2], bh[3]);
                }
            }
        }
        __syncthreads();
        if (kt + 2 < nc) issue(kt + 2, kt & 1);
        cpa_commit();   // always commit to keep group parity for cpa_wait<1>
    }

    // ---- epilogue ----
    #pragma unroll
    for (int mi = 0; mi < 4; mi++) {
        long r0 = bm + wm * 64 + mi * 16 + (lane >> 2);
        #pragma unroll
        for (int ni = 0; ni < 8; ni++) {
            long c = bn + wn * 64 + ni * 8 + 2 * (lane & 3);
            float v0 = alpha * acc[mi][ni][0], v1 = alpha * acc[mi][ni][1];
            float v2 = alpha * acc[mi][ni][2], v3 = alpha * acc[mi][ni][3];
            if (MODE == 0) {
                float* Cb = Cf + (long)blockIdx.z * sC;
                *(float2*)(Cb + r0 * N + c)       = make_float2(v0, v1);
                *(float2*)(Cb + (r0 + 8) * N + c) = make_float2(v2, v3);
            } else {
                __nv_bfloat16* Chb = Ch + (long)blockIdx.z * sC;
                __nv_bfloat16* Clb = Cl + (long)blockIdx.z * sC;
                __nv_bfloat162 h0 = __floats2bfloat162_rn(v0, v1);
                __nv_bfloat162 l0 = __floats2bfloat162_rn(v0 - __low2float(h0),
                                                          v1 - __high2float(h0));
                __nv_bfloat162 h1 = __floats2bfloat162_rn(v2, v3);
                __nv_bfloat162 l1 = __floats2bfloat162_rn(v2 - __low2float(h1),
                                                          v3 - __high2float(h1));
                *(__nv_bfloat162*)(Chb + r0 * N + c)       = h0;
                *(__nv_bfloat162*)(Clb + r0 * N + c)       = l0;
                *(__nv_bfloat162*)(Chb + (r0 + 8) * N + c) = h1;
                *(__nv_bfloat162*)(Clb + (r0 + 8) * N + c) = l1;
            }
        }
    }
}

// ---------------------------------------------------------------------------
// Row softmax over 2048 fp32 scores -> bf16 hi/lo attn. One CTA per row.
// ---------------------------------------------------------------------------
__global__ __launch_bounds__(256) void softmax_split(const float* __restrict__ S,
                                                     __nv_bfloat16* __restrict__ Ph,
                                                     __nv_bfloat16* __restrict__ Pl) {
    const float* row = S + (size_t)blockIdx.x * 2048;
    __nv_bfloat16* ph = Ph + (size_t)blockIdx.x * 2048;
    __nv_bfloat16* pl = Pl + (size_t)blockIdx.x * 2048;
    const int tid = threadIdx.x;
    const int wid = tid >> 5, lane = tid & 31;
    __shared__ float smax[8], ssum[8];

    float v[8];
    #pragma unroll
    for (int i = 0; i < 8; i++) v[i] = row[tid + 256 * i];

    float m = v[0];
    #pragma unroll
    for (int i = 1; i < 8; i++) m = fmaxf(m, v[i]);
    #pragma unroll
    for (int o = 16; o > 0; o >>= 1) m = fmaxf(m, __shfl_xor_sync(0xffffffffu, m, o));
    if (lane == 0) smax[wid] = m;
    __syncthreads();
    m = smax[0];
    #pragma unroll
    for (int w = 1; w < 8; w++) m = fmaxf(m, smax[w]);

    float s = 0.f;
    #pragma unroll
    for (int i = 0; i < 8; i++) { v[i] = __expf(v[i] - m); s += v[i]; }
    #pragma unroll
    for (int o = 16; o > 0; o >>= 1) s += __shfl_xor_sync(0xffffffffu, s, o);
    if (lane == 0) ssum[wid] = s;
    __syncthreads();
    s = 0.f;
    #pragma unroll
    for (int w = 0; w < 8; w++) s += ssum[w];

    float inv = 1.0f / s;
    #pragma unroll
    for (int i = 0; i < 8; i++) {
        float p = v[i] * inv;
        __nv_bfloat16 h = __float2bfloat16(p);
        __nv_bfloat16 l = __float2bfloat16(p - __bfloat162float(h));
        ph[tid + 256 * i] = h;
        pl[tid + 256 * i] = l;
    }
}

// ---------------------------------------------------------------------------
// kernel_launch
// ---------------------------------------------------------------------------
extern "C" void kernel_launch(void* const* d_in, const int* in_sizes, int n_in,
                              void* d_out, int out_size) {
    const float* x = (const float*)d_in[0];   // [4,2048,1024]
    const float* w = (const float*)d_in[1];   // [3,1024,1024]
    float* out = (float*)d_out;               // [4,2048,1024] fp32

    __nv_bfloat16 *xh, *xl, *wth, *wtl, *qkh, *qkl, *vth, *vtl, *ph, *pl;
    float *vv, *scores;
    cudaGetSymbolAddress((void**)&xh, g_xh);
    cudaGetSymbolAddress((void**)&xl, g_xl);
    cudaGetSymbolAddress((void**)&wth, g_wth);
    cudaGetSymbolAddress((void**)&wtl, g_wtl);
    cudaGetSymbolAddress((void**)&qkh, g_qkh);
    cudaGetSymbolAddress((void**)&qkl, g_qkl);
    cudaGetSymbolAddress((void**)&vv, g_v);
    cudaGetSymbolAddress((void**)&vth, g_vth);
    cudaGetSymbolAddress((void**)&vtl, g_vtl);
    cudaGetSymbolAddress((void**)&scores, g_scores);
    cudaGetSymbolAddress((void**)&ph, g_ph);
    cudaGetSymbolAddress((void**)&pl, g_pl);

    static bool attr_done = false;
    if (!attr_done) {
        cudaFuncSetAttribute(gemm_bs<0>, cudaFuncAttributeMaxDynamicSharedMemorySize,
                             SMEM_BYTES);
        cudaFuncSetAttribute(gemm_bs<1>, cudaFuncAttributeMaxDynamicSharedMemorySize,
                             SMEM_BYTES);
        attr_done = true;
    }

    // 1) split x;  transpose+split W
    split_f32<<<8192, 256>>>(x, xh, xl);                     // 8192*1024/4 f4
    transpose_split<<<dim3(32, 32, 3), dim3(32, 8)>>>(w, wth, wtl, 1024, 1024);

    // 2) Q,K = x @ W[0..1]  (bf16 hi/lo out), z=2
    gemm_bs<1><<<dim3(4, 64, 2), 256, SMEM_BYTES>>>(
        xh, xl, wth, wtl, nullptr, qkh, qkl,
        8192, 1024, 1024, 0L, 1024L * 1024, 8192L * 1024, 1.0f);

    // 3) V = x @ W[2]  (fp32 out)
    gemm_bs<0><<<dim3(4, 64, 1), 256, SMEM_BYTES>>>(
        xh, xl, wth + 2L * 1024 * 1024, wtl + 2L * 1024 * 1024, vv, nullptr, nullptr,
        8192, 1024, 1024, 0L, 0L, 0L, 1.0f);

    // 4) V^T split per batch: [2048,1024] -> [1024,2048]
    transpose_split<<<dim3(32, 64, 4), dim3(32, 8)>>>(vv, vth, vtl, 2048, 1024);

    // 5) scores = (Q @ K^T) / 32  (fp32)
    gemm_bs<0><<<dim3(8, 16, 4), 256, SMEM_BYTES>>>(
        qkh, qkl, qkh + 8192L * 1024, qkl + 8192L * 1024, scores, nullptr, nullptr,
        2048, 2048, 1024, 2048L * 1024, 2048L * 1024, 2048L * 2048, 0.03125f);

    // 6) softmax -> attn split
    softmax_split<<<8192, 256>>>(scores, ph, pl);

    // 7) out = attn @ V
    gemm_bs<0><<<dim3(4, 16, 4), 256, SMEM_BYTES>>>(
        ph, pl, vth, vtl, out, nullptr, nullptr,
        2048, 1024, 2048, 2048L * 2048, 1024L * 2048, 2048L * 1024, 1.0f);
}